// round 2
// baseline (speedup 1.0000x reference)
#include <cuda_runtime.h>
#include <math.h>

#define BSZ 4
#define SEQ 2048
#define DMODEL 512
#define NH 8
#define HDIM 64
#define KW1 64
#define KW2 64
#define MROWS (BSZ * SEQ)   // 8192

// ---------------- scratch (device globals; allocation-free) ----------------
__device__ float g_q[(size_t)BSZ * NH * SEQ * HDIM];   // [B,H,L,HD]
__device__ float g_k[(size_t)BSZ * NH * SEQ * HDIM];
__device__ float g_v[(size_t)BSZ * NH * SEQ * HDIM];
__device__ float g_u[(size_t)BSZ * SEQ * DMODEL];      // [B,L,D]
__device__ float g_g[(size_t)BSZ * SEQ * DMODEL];      // silu(attn)*u, [B,L,D]

// ---------------- SGEMM: C[M,N] = A[M,K] @ B[N,K]^T + bias ----------------
// MODE 0: A=x, B = concat(w_qkv[1536,K], w_u[512,K]); epilogue scatters
//         q,k,v -> [B,H,L,HD] and u -> [B,L,D].
// MODE 1: A=g_g (device global), B=w_out; epilogue writes C + bias.
template <int MODE>
__global__ void __launch_bounds__(256)
sgemm_kernel(const float* __restrict__ A,
             const float* __restrict__ B1,
             const float* __restrict__ B2,
             const float* __restrict__ bias1,
             const float* __restrict__ bias2,
             float* __restrict__ C,
             int N, int K)
{
    __shared__ float As[8][128];
    __shared__ float Bs[8][128];

    const int tid = threadIdx.x;
    const int m0 = blockIdx.y * 128;
    const int n0 = blockIdx.x * 128;

    const float* Aptr = (MODE == 1) ? g_g : A;

    const int lr = tid >> 1;          // 0..127 row within tile
    const int lc = (tid & 1) << 2;    // 0 or 4 (float4 column)

    const float* arow = Aptr + (size_t)(m0 + lr) * K + lc;
    const int gn = n0 + lr;
    const float* brow;
    if (MODE == 0 && gn >= 1536)
        brow = B2 + (size_t)(gn - 1536) * K + lc;
    else
        brow = B1 + (size_t)gn * K + lc;

    const int ty = tid >> 4;          // 0..15
    const int tx = tid & 15;          // 0..15

    float acc[8][8];
#pragma unroll
    for (int i = 0; i < 8; i++)
#pragma unroll
        for (int j = 0; j < 8; j++) acc[i][j] = 0.f;

    for (int k0 = 0; k0 < K; k0 += 8) {
        float4 av = *(const float4*)(arow + k0);
        float4 bv = *(const float4*)(brow + k0);
        __syncthreads();
        As[lc + 0][lr] = av.x; As[lc + 1][lr] = av.y;
        As[lc + 2][lr] = av.z; As[lc + 3][lr] = av.w;
        Bs[lc + 0][lr] = bv.x; Bs[lc + 1][lr] = bv.y;
        Bs[lc + 2][lr] = bv.z; Bs[lc + 3][lr] = bv.w;
        __syncthreads();
#pragma unroll
        for (int kk = 0; kk < 8; kk++) {
            float a[8], b[8];
            *(float4*)(a)     = *(const float4*)(&As[kk][ty * 8]);
            *(float4*)(a + 4) = *(const float4*)(&As[kk][ty * 8 + 4]);
            *(float4*)(b)     = *(const float4*)(&Bs[kk][tx * 8]);
            *(float4*)(b + 4) = *(const float4*)(&Bs[kk][tx * 8 + 4]);
#pragma unroll
            for (int i = 0; i < 8; i++)
#pragma unroll
                for (int j = 0; j < 8; j++) acc[i][j] += a[i] * b[j];
        }
    }

    // ---------------- epilogue ----------------
#pragma unroll
    for (int ii = 0; ii < 8; ii++) {
        const int m = m0 + ty * 8 + ii;
        if (MODE == 0) {
            const int b = m >> 11;        // m / SEQ
            const int l = m & 2047;       // m % SEQ
#pragma unroll
            for (int jj = 0; jj < 8; jj++) {
                const int n = n0 + tx * 8 + jj;
                float v = acc[ii][jj];
                if (n < 1536) {
                    v += bias1[n];
                    const int s = n >> 9;             // 0=q,1=k,2=v
                    const int h = (n >> 6) & 7;
                    const int d = n & 63;
                    float* dst = (s == 0) ? g_q : (s == 1) ? g_k : g_v;
                    dst[((((size_t)b * NH + h) * SEQ) + l) * HDIM + d] = v;
                } else {
                    v += bias2[n - 1536];
                    g_u[(size_t)m * DMODEL + (n - 1536)] = v;
                }
            }
        } else {
#pragma unroll
            for (int jj = 0; jj < 8; jj++) {
                const int n = n0 + tx * 8 + jj;
                C[(size_t)m * N + n] = acc[ii][jj] + bias1[n];
            }
        }
    }
}

// ---------------- sparse semi-local attention + SiLU gate ----------------
// One warp per (b,h,i). Allowed keys for query i:
//   glob:  j in [0, g_hi],  g_hi = min(K2, L-i, i)
//   band:  j in [max(L-K1-i, g_hi+1), min(i, L-i)]   (dedup'd vs glob)
// n_keys <= 130.
__global__ void __launch_bounds__(256)
attn_kernel()
{
    const int warp = (blockIdx.x * blockDim.x + threadIdx.x) >> 5;
    const int lane = threadIdx.x & 31;
    const int i  = warp & (SEQ - 1);
    const int bh = warp >> 11;            // b*NH + h, 0..31

    const float* qrow = g_q + ((size_t)bh * SEQ + i) * HDIM;
    const float2 qv = *(const float2*)(qrow + (lane << 1));

    const int g_hi   = min(min(KW2, SEQ - i), i);
    const int band_lo = max(SEQ - KW1 - i, g_hi + 1);
    const int band_hi = min(i, SEQ - i);
    const int nb = max(0, band_hi - band_lo + 1);
    const int n_keys = g_hi + 1 + nb;

    const float* kbase = g_k + (size_t)bh * SEQ * HDIM;
    const float* vbase = g_v + (size_t)bh * SEQ * HDIM;
    const float scale = 0.125f;   // 1/sqrt(64)

    float sc[5];
#pragma unroll
    for (int s = 0; s < 5; s++) sc[s] = -INFINITY;

    // ---- QK^T (4 keys per butterfly round for ILP) ----
#pragma unroll
    for (int s = 0; s < 5; s++) {
        const int tbase = s * 32;
        if (tbase < n_keys) {
            float mysc = -INFINITY;
            for (int r0 = 0; r0 < 32 && tbase + r0 < n_keys; r0 += 4) {
                float p[4];
#pragma unroll
                for (int u = 0; u < 4; u++) {
                    const int t = tbase + r0 + u;
                    float pr = 0.f;
                    if (t < n_keys) {
                        const int j = (t <= g_hi) ? t : band_lo + (t - g_hi - 1);
                        const float2 kv2 =
                            *(const float2*)(kbase + (size_t)j * HDIM + (lane << 1));
                        pr = qv.x * kv2.x + qv.y * kv2.y;
                    }
                    p[u] = pr;
                }
#pragma unroll
                for (int off = 16; off; off >>= 1) {
                    p[0] += __shfl_xor_sync(0xffffffffu, p[0], off);
                    p[1] += __shfl_xor_sync(0xffffffffu, p[1], off);
                    p[2] += __shfl_xor_sync(0xffffffffu, p[2], off);
                    p[3] += __shfl_xor_sync(0xffffffffu, p[3], off);
                }
#pragma unroll
                for (int u = 0; u < 4; u++) {
                    if (tbase + r0 + u < n_keys && lane == r0 + u)
                        mysc = p[u] * scale;
                }
            }
            sc[s] = mysc;
        }
    }

    // ---- softmax over the (distributed) scores ----
    float m = sc[0];
#pragma unroll
    for (int s = 1; s < 5; s++) m = fmaxf(m, sc[s]);
#pragma unroll
    for (int off = 16; off; off >>= 1)
        m = fmaxf(m, __shfl_xor_sync(0xffffffffu, m, off));

    float pe[5];
    float lsum = 0.f;
#pragma unroll
    for (int s = 0; s < 5; s++) {
        pe[s] = __expf(sc[s] - m);        // sc=-inf -> 0
        lsum += pe[s];
    }
#pragma unroll
    for (int off = 16; off; off >>= 1)
        lsum += __shfl_xor_sync(0xffffffffu, lsum, off);
    const float inv_denom = 1.f / lsum;

    // ---- P @ V ----
    float o0 = 0.f, o1 = 0.f;
#pragma unroll
    for (int s = 0; s < 5; s++) {
        const int tbase = s * 32;
        if (tbase < n_keys) {
            const float myp = pe[s];
            const int tmax = min(32, n_keys - tbase);
            for (int r = 0; r < tmax; r++) {
                const float pt = __shfl_sync(0xffffffffu, myp, r);
                const int t = tbase + r;
                const int j = (t <= g_hi) ? t : band_lo + (t - g_hi - 1);
                const float2 vv =
                    *(const float2*)(vbase + (size_t)j * HDIM + (lane << 1));
                o0 += pt * vv.x;
                o1 += pt * vv.y;
            }
        }
    }
    o0 *= inv_denom;
    o1 *= inv_denom;

    // ---- SiLU gate fused: g = silu(o) * u ----
    const int b = bh >> 3;
    const int h = bh & 7;
    const size_t uidx =
        ((size_t)(b * SEQ + i)) * DMODEL + h * HDIM + (lane << 1);
    const float2 uu = *(const float2*)(g_u + uidx);
    float2 out;
    out.x = (o0 / (1.f + __expf(-o0))) * uu.x;
    out.y = (o1 / (1.f + __expf(-o1))) * uu.y;
    *(float2*)(g_g + uidx) = out;
}

// ---------------- launch ----------------
extern "C" void kernel_launch(void* const* d_in, const int* in_sizes, int n_in,
                              void* d_out, int out_size)
{
    const float* x     = (const float*)d_in[0];
    const float* w_qkv = (const float*)d_in[1];
    const float* b_qkv = (const float*)d_in[2];
    const float* w_u   = (const float*)d_in[3];
    const float* b_u   = (const float*)d_in[4];
    const float* w_out = (const float*)d_in[5];
    const float* b_out = (const float*)d_in[6];
    float* out = (float*)d_out;

    // Fused QKV+U projection: [8192,512] @ [2048,512]^T
    {
        dim3 grid(2048 / 128, MROWS / 128);
        sgemm_kernel<0><<<grid, 256>>>(x, w_qkv, w_u, b_qkv, b_u,
                                       nullptr, 2048, DMODEL);
    }

    // Sparse attention + SiLU*u gate: 65536 warps
    {
        const int warps = BSZ * NH * SEQ;          // 65536
        attn_kernel<<<warps / 8, 256>>>();
    }

    // Output projection: [8192,512] @ [512,512]^T
    {
        dim3 grid(DMODEL / 128, MROWS / 128);
        sgemm_kernel<1><<<grid, 256>>>(nullptr, w_out, nullptr, b_out,
                                       nullptr, out, DMODEL, DMODEL);
    }
}